// round 9
// baseline (speedup 1.0000x reference)
#include <cuda_runtime.h>
#include <cuda_fp16.h>
#include <math_constants.h>
#include <cstdint>

// Round 9: warp-specialized fusion — mask generation runs CONCURRENTLY with
// attention inside each CTA.
//   CTA = 256 thr: warps 0-3 = attention (BM=64, identical math to round 8),
//                  warps 4-7 = threefry producers -> 1KB smem ring (2 stages),
//   named-barrier full/empty protocol; attn-internal syncs use bar.sync 1,128.
//   Each SMSP: 1 tensor warp + 1 ALU warp -> mask's ~270us/SM of ALU work
//   hides in the tensor warp's idle issue slots. Eliminates the 300us mask kernel.
// rel_err bit-identical: ~1.5387e-4.

#define S_LEN 2048
#define D_DIM 128
#define BM 64
#define BN 64
#define NT 128                          // attn (consumer) threads
#define NELEM (2 * 16 * S_LEN * D_DIM)

#define TILE_B 17408                    // one 64x128 fp16 tile (64*272)
#define KBUF_B (2 * TILE_B)
#define OFF_K0 0
#define OFF_K1 KBUF_B                   // 34816
#define OFF_V  (2 * KBUF_B)             // 69632
#define OFF_MK (OFF_V + TILE_B)         // 87040: mask ring (2 x 128 words)
#define SMEM_BYTES (OFF_MK + 1024)      // 88064

__device__ __half g_Kh[NELEM];
__device__ __half g_Kl[NELEM];
__device__ __half g_Vh[NELEM];

#define BAR_SYNC(id, n)   asm volatile("bar.sync %0, %1;"   :: "r"(id), "r"(n) : "memory")
#define BAR_ARRIVE(id, n) asm volatile("bar.arrive %0, %1;" :: "r"(id), "r"(n) : "memory")

// ---------------- prologue: fp32 -> fp16 hi/lo conversion ----------------
__global__ void __launch_bounds__(256, 4)
convert_kernel(const float* __restrict__ x1, const float* __restrict__ x2)
{
    int stride = gridDim.x * blockDim.x;
    for (int i = blockIdx.x * blockDim.x + threadIdx.x; i < NELEM / 4; i += stride) {
        float4 k = reinterpret_cast<const float4*>(x2)[i];
        float4 v = reinterpret_cast<const float4*>(x1)[i];
        __half h0 = __float2half_rn(k.x), h1 = __float2half_rn(k.y);
        __half h2 = __float2half_rn(k.z), h3 = __float2half_rn(k.w);
        __half e0 = __float2half_rn(k.x - __half2float(h0));
        __half e1 = __float2half_rn(k.y - __half2float(h1));
        __half e2 = __float2half_rn(k.z - __half2float(h2));
        __half e3 = __float2half_rn(k.w - __half2float(h3));
        reinterpret_cast<__half2*>(g_Kh)[2*i]   = __halves2half2(h0, h1);
        reinterpret_cast<__half2*>(g_Kh)[2*i+1] = __halves2half2(h2, h3);
        reinterpret_cast<__half2*>(g_Kl)[2*i]   = __halves2half2(e0, e1);
        reinterpret_cast<__half2*>(g_Kl)[2*i+1] = __halves2half2(e2, e3);
        reinterpret_cast<__half2*>(g_Vh)[2*i] =
            __halves2half2(__float2half_rn(v.x), __float2half_rn(v.y));
        reinterpret_cast<__half2*>(g_Vh)[2*i+1] =
            __halves2half2(__float2half_rn(v.z), __float2half_rn(v.w));
    }
}

// ---------------- threefry (JAX partitionable, key=(0,42)) ----------------
__device__ __forceinline__ unsigned tf_rotl(unsigned x, int r) {
    return __funnelshift_l(x, x, r);
}
__device__ __forceinline__ unsigned threefry_bits_part(unsigned g) {
    const unsigned ks1 = 42u;
    const unsigned ks2 = 0x1BD11BDAu ^ 42u;
    unsigned x0 = 0u;
    unsigned x1 = g + ks1;
#define TF_ROUND(r) { x0 += x1; x1 = tf_rotl(x1, (r)) ^ x0; }
    TF_ROUND(13) TF_ROUND(15) TF_ROUND(26) TF_ROUND(6)
    x0 += ks1; x1 += ks2 + 1u;
    TF_ROUND(17) TF_ROUND(29) TF_ROUND(16) TF_ROUND(24)
    x0 += ks2; x1 += 0u + 2u;
    TF_ROUND(13) TF_ROUND(15) TF_ROUND(26) TF_ROUND(6)
    x0 += 0u; x1 += ks1 + 3u;
    TF_ROUND(17) TF_ROUND(29) TF_ROUND(16) TF_ROUND(24)
    x0 += ks1; x1 += ks2 + 4u;
    TF_ROUND(13) TF_ROUND(15) TF_ROUND(26) TF_ROUND(6)
    x0 += ks2; x1 += 0u + 5u;
#undef TF_ROUND
    return x0 ^ x1;
}

__device__ __forceinline__ uint32_t packh2(__half a, __half b) {
    __half2 h = __halves2half2(a, b);
    return *reinterpret_cast<uint32_t*>(&h);
}
__device__ __forceinline__ void mma_f16(float c[4], const uint32_t a[4],
                                        uint32_t b0, uint32_t b1) {
    asm volatile(
        "mma.sync.aligned.m16n8k16.row.col.f32.f16.f16.f32 "
        "{%0,%1,%2,%3}, {%4,%5,%6,%7}, {%8,%9}, {%0,%1,%2,%3};\n"
        : "+f"(c[0]), "+f"(c[1]), "+f"(c[2]), "+f"(c[3])
        : "r"(a[0]), "r"(a[1]), "r"(a[2]), "r"(a[3]), "r"(b0), "r"(b1));
}
__device__ __forceinline__ void ldsm_x4(uint32_t& r0, uint32_t& r1,
                                        uint32_t& r2, uint32_t& r3, uint32_t addr) {
    asm volatile("ldmatrix.sync.aligned.m8n8.x4.shared.b16 {%0,%1,%2,%3}, [%4];"
                 : "=r"(r0), "=r"(r1), "=r"(r2), "=r"(r3) : "r"(addr));
}
__device__ __forceinline__ void ldsm_x4_t(uint32_t& r0, uint32_t& r1,
                                          uint32_t& r2, uint32_t& r3, uint32_t addr) {
    asm volatile("ldmatrix.sync.aligned.m8n8.x4.trans.shared.b16 {%0,%1,%2,%3}, [%4];"
                 : "=r"(r0), "=r"(r1), "=r"(r2), "=r"(r3) : "r"(addr));
}
__device__ __forceinline__ void cp_async16(uint32_t dst, const void* src) {
    asm volatile("cp.async.cg.shared.global [%0], [%1], 16;" :: "r"(dst), "l"(src));
}
__device__ __forceinline__ void cp_commit() { asm volatile("cp.async.commit_group;"); }
template <int N> __device__ __forceinline__ void cp_wait() {
    asm volatile("cp.async.wait_group %0;" :: "n"(N));
}

__device__ __forceinline__ void stage_k(uint32_t buf_b, int bh, int k0, int tid)
{
    const size_t kbase = (size_t)bh * (S_LEN * D_DIM) + (size_t)k0 * D_DIM;
    #pragma unroll
    for (int it = 0; it < 16; ++it) {
        int id  = tid + it * NT;
        int arr = id >> 10;
        int rem = id & 1023;
        int row = rem >> 4;
        int col = rem & 15;
        uint32_t dst = buf_b + (uint32_t)(arr * TILE_B + row * 272 + col * 16);
        const __half* src = (arr ? g_Kl : g_Kh) + kbase + (size_t)row * D_DIM + col * 8;
        cp_async16(dst, src);
    }
}
__device__ __forceinline__ void stage_v(uint32_t vbuf_b, int bh, int k0, int tid)
{
    const size_t kbase = (size_t)bh * (S_LEN * D_DIM) + (size_t)k0 * D_DIM;
    #pragma unroll
    for (int it = 0; it < 8; ++it) {
        int id  = tid + it * NT;
        int row = id >> 4;
        int col = id & 15;
        cp_async16(vbuf_b + (uint32_t)(row * 272 + col * 16),
                   g_Vh + kbase + (size_t)row * D_DIM + col * 8);
    }
}

__global__ void __launch_bounds__(256, 1)
attn_fused_kernel(const float* __restrict__ x1,
                  const float* __restrict__ x2,
                  const float* __restrict__ x3,
                  float* __restrict__ out)
{
    extern __shared__ __half smh[];
    uint32_t* mk = reinterpret_cast<uint32_t*>(
        reinterpret_cast<char*>(smh) + OFF_MK);

    const int tid  = threadIdx.x;
    const int warp = tid >> 5;
    const int lane = tid & 31;
    const int bh   = blockIdx.y;
    const int q0   = blockIdx.x * BM;

    // ================= producer warps (4-7): threefry mask ring =================
    if (warp >= 4) {
        const int ptid = tid - 128;                  // 0..127
        const unsigned pw = (unsigned)(ptid >> 5);   // attn warp fed
        const unsigned pl = (unsigned)(ptid & 31);
        const unsigned pg = pl >> 2, pc = pl & 3u;
        const unsigned qrow = (unsigned)q0 + pw * 16u + pg;
        const unsigned gbase = ((unsigned)bh * 2048u + qrow) * 2048u + 2u * pc;

        for (int kt = 0; kt < 32; ++kt) {
            const int b = kt & 1;
            if (kt >= 2) BAR_SYNC(4 + b, 256);       // consumers freed buffer b
            const unsigned gt = gbase + (unsigned)(kt * 64);
            uint32_t keepbits = 0u;
            #pragma unroll
            for (int n = 0; n < 8; ++n) {
                unsigned gi = gt + (unsigned)(8 * n);
                unsigned b00 = threefry_bits_part(gi);
                unsigned b01 = threefry_bits_part(gi + 1u);
                unsigned b10 = threefry_bits_part(gi + 16384u);
                unsigned b11 = threefry_bits_part(gi + 16385u);
                keepbits |= ((~b00) >> 31) << (4 * n + 0);
                keepbits |= ((~b01) >> 31) << (4 * n + 1);
                keepbits |= ((~b10) >> 31) << (4 * n + 2);
                keepbits |= ((~b11) >> 31) << (4 * n + 3);
            }
            mk[b * 128 + ptid] = keepbits;
            __threadfence_block();
            BAR_ARRIVE(2 + b, 256);                  // publish full(b)
        }
        return;
    }

    // ================= consumer warps (0-3): attention =================
    const int g = lane >> 2;
    const int c = lane & 3;
    const int qrow = q0 + warp * 16 + g;

    const float* Q = x1 + (size_t)bh * (S_LEN * D_DIM);
    const float* R = x2 + (size_t)bh * (S_LEN * D_DIM);
    float* O = out + (size_t)bh * (S_LEN * D_DIM);
    const float scl = (1.0f / x3[bh]) * 1.4426950408889634f;

    const uint32_t smem_u32 = (uint32_t)__cvta_generic_to_shared(smh);

    // prologue: stage K(0)
    stage_k(smem_u32 + OFF_K0, bh, 0, tid);
    cp_commit();

    // ---- Q fragments resident (hi + lo split) ----
    uint32_t qh[8][4], ql[8][4];
    #pragma unroll
    for (int t = 0; t < 8; ++t) {
        #pragma unroll
        for (int p = 0; p < 4; ++p) {
            int row = qrow + (p & 1) * 8;
            int col = 16 * t + (p >> 1) * 8 + 2 * c;
            float2 v = *reinterpret_cast<const float2*>(Q + (size_t)row * D_DIM + col);
            __half hx = __float2half_rn(v.x), hy = __float2half_rn(v.y);
            __half lx = __float2half_rn(v.x - __half2float(hx));
            __half ly = __float2half_rn(v.y - __half2float(hy));
            qh[t][p] = packh2(hx, hy);
            ql[t][p] = packh2(lx, ly);
        }
    }

    float oacc[16][4];
    #pragma unroll
    for (int i = 0; i < 16; ++i)
        #pragma unroll
        for (int j = 0; j < 4; ++j) oacc[i][j] = 0.0f;
    float m0 = -CUDART_INF_F, m1 = -CUDART_INF_F;
    float l0 = 0.0f, l1 = 0.0f;

    const int lr  = lane & 7;
    const int seg = lane >> 3;
    const uint32_t k_lane_off = (uint32_t)(lr * 272 + ((seg & 1) * 8 + (seg >> 1) * 16) * 2);
    const uint32_t v_lane_off = (uint32_t)(((seg & 1) * 8 + lr) * 272 + ((seg >> 1) * 8) * 2);
    const uint32_t kh_base0 = smem_u32 + k_lane_off;
    const uint32_t kl_base0 = smem_u32 + (uint32_t)TILE_B + k_lane_off;
    const uint32_t vh_base  = smem_u32 + (uint32_t)OFF_V + v_lane_off;

    for (int kt = 0; kt < 32; ++kt) {
        const int b = kt & 1;
        const uint32_t cur = (uint32_t)b * KBUF_B;

        // attn warps done reading V(kt-1) and the K buffer we overwrite
        BAR_SYNC(1, 128);

        stage_v(smem_u32 + OFF_V, bh, kt * BN, tid);
        cp_commit();
        if (kt + 1 < 32)
            stage_k(smem_u32 + ((kt & 1) ? OFF_K0 : OFF_K1), bh, (kt + 1) * BN, tid);
        cp_commit();

        cp_wait<2>();     // K(kt) resident
        BAR_SYNC(1, 128);

        const uint32_t kh_base = kh_base0 + cur;
        const uint32_t kl_base = kl_base0 + cur;

        // ---- S = Q @ K^T (qh*kh + ql*kh + qh*kl) ----
        float sacc[8][4];
        #pragma unroll
        for (int n = 0; n < 8; ++n) {
            sacc[n][0] = 0.0f; sacc[n][1] = 0.0f;
            sacc[n][2] = 0.0f; sacc[n][3] = 0.0f;
            const uint32_t rowoff = (uint32_t)(n * 8 * 272);
            #pragma unroll
            for (int dp = 0; dp < 4; ++dp) {
                uint32_t bh0, bh1, bh2, bh3, bl0, bl1, bl2, bl3;
                ldsm_x4(bh0, bh1, bh2, bh3, kh_base + rowoff + (uint32_t)(dp * 64));
                ldsm_x4(bl0, bl1, bl2, bl3, kl_base + rowoff + (uint32_t)(dp * 64));
                mma_f16(sacc[n], qh[2 * dp],     bh0, bh1);
                mma_f16(sacc[n], qh[2 * dp + 1], bh2, bh3);
                mma_f16(sacc[n], ql[2 * dp],     bh0, bh1);
                mma_f16(sacc[n], ql[2 * dp + 1], bh2, bh3);
                mma_f16(sacc[n], qh[2 * dp],     bl0, bl1);
                mma_f16(sacc[n], qh[2 * dp + 1], bl2, bl3);
            }
        }

        // ---- online softmax (exp2 domain) ----
        float mx0 = -CUDART_INF_F, mx1 = -CUDART_INF_F;
        #pragma unroll
        for (int n = 0; n < 8; ++n) {
            sacc[n][0] *= scl; sacc[n][1] *= scl;
            sacc[n][2] *= scl; sacc[n][3] *= scl;
            mx0 = fmaxf(mx0, fmaxf(sacc[n][0], sacc[n][1]));
            mx1 = fmaxf(mx1, fmaxf(sacc[n][2], sacc[n][3]));
        }
        mx0 = fmaxf(mx0, __shfl_xor_sync(0xffffffffu, mx0, 1));
        mx0 = fmaxf(mx0, __shfl_xor_sync(0xffffffffu, mx0, 2));
        mx1 = fmaxf(mx1, __shfl_xor_sync(0xffffffffu, mx1, 1));
        mx1 = fmaxf(mx1, __shfl_xor_sync(0xffffffffu, mx1, 2));
        float mn0 = fmaxf(m0, mx0), mn1 = fmaxf(m1, mx1);
        float sc0 = exp2f(m0 - mn0), sc1 = exp2f(m1 - mn1);
        m0 = mn0; m1 = mn1;
        float rs0 = 0.0f, rs1 = 0.0f;
        #pragma unroll
        for (int n = 0; n < 8; ++n) {
            sacc[n][0] = exp2f(sacc[n][0] - mn0);
            sacc[n][1] = exp2f(sacc[n][1] - mn0);
            sacc[n][2] = exp2f(sacc[n][2] - mn1);
            sacc[n][3] = exp2f(sacc[n][3] - mn1);
            rs0 += sacc[n][0] + sacc[n][1];
            rs1 += sacc[n][2] + sacc[n][3];
        }
        rs0 += __shfl_xor_sync(0xffffffffu, rs0, 1);
        rs0 += __shfl_xor_sync(0xffffffffu, rs0, 2);
        rs1 += __shfl_xor_sync(0xffffffffu, rs1, 1);
        rs1 += __shfl_xor_sync(0xffffffffu, rs1, 2);
        l0 = l0 * sc0 + rs0;
        l1 = l1 * sc1 + rs1;
        #pragma unroll
        for (int i = 0; i < 16; ++i) {
            oacc[i][0] *= sc0; oacc[i][1] *= sc0;
            oacc[i][2] *= sc1; oacc[i][3] *= sc1;
        }

        // ---- mask from producer ring: wait full(b), pack, release empty(b) ----
        BAR_SYNC(2 + b, 256);
        uint32_t keepbits = mk[b * 128 + (warp << 5) + lane];
        uint32_t pfr[8][2];
        #pragma unroll
        for (int n = 0; n < 8; ++n) {
            float p00 = ((keepbits >> (4 * n + 0)) & 1u) ? sacc[n][0] : 0.0f;
            float p01 = ((keepbits >> (4 * n + 1)) & 1u) ? sacc[n][1] : 0.0f;
            float p10 = ((keepbits >> (4 * n + 2)) & 1u) ? sacc[n][2] : 0.0f;
            float p11 = ((keepbits >> (4 * n + 3)) & 1u) ? sacc[n][3] : 0.0f;
            pfr[n][0] = packh2(__float2half_rn(p00), __float2half_rn(p01));
            pfr[n][1] = packh2(__float2half_rn(p10), __float2half_rn(p11));
        }
        BAR_ARRIVE(4 + b, 256);

        cp_wait<1>();     // V(kt) resident
        BAR_SYNC(1, 128);

        // ---- O += P @ V ----
        #pragma unroll
        for (int kk = 0; kk < 4; ++kk) {
            uint32_t a[4] = { pfr[2 * kk][0], pfr[2 * kk][1],
                              pfr[2 * kk + 1][0], pfr[2 * kk + 1][1] };
            const uint32_t kkoff = (uint32_t)(kk * 16 * 272);
            #pragma unroll
            for (int np = 0; np < 8; ++np) {
                uint32_t b0, b1, b2, b3;
                ldsm_x4_t(b0, b1, b2, b3, vh_base + kkoff + (uint32_t)(np * 32));
                mma_f16(oacc[2 * np],     a, b0, b1);
                mma_f16(oacc[2 * np + 1], a, b2, b3);
            }
        }
    }

    // ---- epilogue: out = 2*o/l + residual(x2) ----
    const float il0 = 2.0f / l0;
    const float il1 = 2.0f / l1;
    #pragma unroll
    for (int np = 0; np < 16; ++np) {
        int col = 8 * np + 2 * c;
        const float2 r0 = *reinterpret_cast<const float2*>(R + (size_t)qrow * D_DIM + col);
        const float2 r1 = *reinterpret_cast<const float2*>(R + (size_t)(qrow + 8) * D_DIM + col);
        float2 w0, w1;
        w0.x = fmaf(oacc[np][0], il0, r0.x);
        w0.y = fmaf(oacc[np][1], il0, r0.y);
        w1.x = fmaf(oacc[np][2], il1, r1.x);
        w1.y = fmaf(oacc[np][3], il1, r1.y);
        *reinterpret_cast<float2*>(O + (size_t)qrow * D_DIM + col) = w0;
        *reinterpret_cast<float2*>(O + (size_t)(qrow + 8) * D_DIM + col) = w1;
    }
}

extern "C" void kernel_launch(void* const* d_in, const int* in_sizes, int n_in,
                              void* d_out, int out_size) {
    const float* x1 = (const float*)d_in[0];
    const float* x2 = (const float*)d_in[1];
    const float* x3 = (const float*)d_in[2];
    float* out = (float*)d_out;
    (void)in_sizes; (void)n_in; (void)out_size;

    cudaFuncSetAttribute(attn_fused_kernel,
                         cudaFuncAttributeMaxDynamicSharedMemorySize, SMEM_BYTES);

    convert_kernel<<<1024, 256>>>(x1, x2);
    dim3 grid(S_LEN / BM, 32);    // (32 q-tiles, 32 bh)
    attn_fused_kernel<<<grid, 256, SMEM_BYTES>>>(x1, x2, x3, out);
}

// round 10
// speedup vs baseline: 1.2857x; 1.2857x over previous
#include <cuda_runtime.h>
#include <cuda_fp16.h>
#include <math_constants.h>
#include <cstdint>

// Round 10: R8 structure (convert + mask + attn), mask kernel pipe-balanced.
//  - threefry rotl for 12 of 20 rounds computed as mul.lo|mul.hi with the
//    2^r multipliers LOADED FROM GLOBAL MEMORY (ptxas cannot strength-reduce
//    a loaded operand back to SHF) -> ~12 alu-ops/call move to the fma pipe.
//    alu/call ~50 -> ~38; mask kernel is alu-floor-bound so ~0.76x time.
//  - attn kernel identical to round 8 (718.5us best).
// Mask bits unchanged -> rel_err bit-identical ~1.5387e-4.

#define S_LEN 2048
#define D_DIM 128
#define BM 64
#define BN 64
#define NT 128
#define NELEM (2 * 16 * S_LEN * D_DIM)
#define NMASKW (1 << 22)

#define TILE_B 17408                    // one 64x128 fp16 tile (64*272)
#define KBUF_B (2 * TILE_B)
#define OFF_K0 0
#define OFF_K1 KBUF_B                   // 34816
#define OFF_V  (2 * KBUF_B)             // 69632
#define SMEM_BYTES (OFF_V + TILE_B)     // 87040

__device__ __half g_Kh[NELEM];
__device__ __half g_Kl[NELEM];
__device__ __half g_Vh[NELEM];
__device__ uint32_t g_mask[NMASKW];
// 2^r multipliers for threefry rotations 13,15,26,6 (loaded at runtime so
// ptxas emits IMAD, not SHF)
__device__ uint32_t g_pow2[4] = { 1u << 13, 1u << 15, 1u << 26, 1u << 6 };

// ---------------- prologue: fp32 -> fp16 hi/lo conversion ----------------
__global__ void __launch_bounds__(256, 4)
convert_kernel(const float* __restrict__ x1, const float* __restrict__ x2)
{
    int stride = gridDim.x * blockDim.x;
    for (int i = blockIdx.x * blockDim.x + threadIdx.x; i < NELEM / 4; i += stride) {
        float4 k = reinterpret_cast<const float4*>(x2)[i];
        float4 v = reinterpret_cast<const float4*>(x1)[i];
        __half h0 = __float2half_rn(k.x), h1 = __float2half_rn(k.y);
        __half h2 = __float2half_rn(k.z), h3 = __float2half_rn(k.w);
        __half e0 = __float2half_rn(k.x - __half2float(h0));
        __half e1 = __float2half_rn(k.y - __half2float(h1));
        __half e2 = __float2half_rn(k.z - __half2float(h2));
        __half e3 = __float2half_rn(k.w - __half2float(h3));
        reinterpret_cast<__half2*>(g_Kh)[2*i]   = __halves2half2(h0, h1);
        reinterpret_cast<__half2*>(g_Kh)[2*i+1] = __halves2half2(h2, h3);
        reinterpret_cast<__half2*>(g_Kl)[2*i]   = __halves2half2(e0, e1);
        reinterpret_cast<__half2*>(g_Kl)[2*i+1] = __halves2half2(e2, e3);
        reinterpret_cast<__half2*>(g_Vh)[2*i] =
            __halves2half2(__float2half_rn(v.x), __float2half_rn(v.y));
        reinterpret_cast<__half2*>(g_Vh)[2*i+1] =
            __halves2half2(__float2half_rn(v.z), __float2half_rn(v.w));
    }
}

// ---------------- threefry (JAX partitionable, key=(0,42)) ----------------
// rotl via runtime-multiplier IMAD pair (fma pipe): lo = x*2^r, hi = x>>(32-r)
// = mulhi(x, 2^r); (lo|hi)^x0 fuses to one LOP3 (alu pipe).
__device__ __forceinline__ unsigned rotmix(unsigned x, unsigned p, unsigned x0) {
    unsigned lo, hi;
    asm("mul.lo.u32 %0, %1, %2;" : "=r"(lo) : "r"(x), "r"(p));
    asm("mul.hi.u32 %0, %1, %2;" : "=r"(hi) : "r"(x), "r"(p));
    return (lo | hi) ^ x0;
}
__device__ __forceinline__ unsigned tf_rotl(unsigned x, int r) {
    return __funnelshift_l(x, x, r);
}
// mixed-pipe threefry: groups 1/3/5 (rot 13,15,26,6) in mul-form,
// groups 2/4 (rot 17,29,16,24) in shf-form.
__device__ __forceinline__ unsigned threefry_bits_mixed(
    unsigned g, unsigned p13, unsigned p15, unsigned p26, unsigned p6)
{
    const unsigned ks1 = 42u;
    const unsigned ks2 = 0x1BD11BDAu ^ 42u;
    unsigned x0 = 0u;
    unsigned x1 = g + ks1;
#define TFR_M(p) { x0 += x1; x1 = rotmix(x1, (p), x0); }
#define TFR_S(r) { x0 += x1; x1 = tf_rotl(x1, (r)) ^ x0; }
    TFR_M(p13) TFR_M(p15) TFR_M(p26) TFR_M(p6)
    x0 += ks1; x1 += ks2 + 1u;
    TFR_S(17) TFR_S(29) TFR_S(16) TFR_S(24)
    x0 += ks2; x1 += 0u + 2u;
    TFR_M(p13) TFR_M(p15) TFR_M(p26) TFR_M(p6)
    x0 += 0u; x1 += ks1 + 3u;
    TFR_S(17) TFR_S(29) TFR_S(16) TFR_S(24)
    x0 += ks1; x1 += ks2 + 4u;
    TFR_M(p13) TFR_M(p15) TFR_M(p26) TFR_M(p6)
    x0 += ks2; x1 += 0u + 5u;
#undef TFR_M
#undef TFR_S
    return x0 ^ x1;
}

// ---------------- mask kernel (BM=64 fragment layout) ----------------
// word idx = ((((bh*32 + qtile)*4 + warp)*32 + kt)*32 + lane
// lane -> (g = lane>>2, c = lane&3); qrow = qtile*64 + warp*16 + g
// bit 4n+{0,1,2,3} <-> g-index gt+8n+{0,1,16384,16385},
// gt = (bh*2048 + qrow)*2048 + 2c + kt*64.
__global__ void __launch_bounds__(256)
mask_kernel()
{
    const unsigned p13 = g_pow2[0], p15 = g_pow2[1];
    const unsigned p26 = g_pow2[2], p6  = g_pow2[3];

    unsigned idx = blockIdx.x * 256u + threadIdx.x;
    unsigned lane  = idx & 31u;
    unsigned kt    = (idx >> 5) & 31u;
    unsigned warp  = (idx >> 10) & 3u;
    unsigned qtile = (idx >> 12) & 31u;
    unsigned bh    = idx >> 17;
    unsigned g = lane >> 2, c = lane & 3u;
    unsigned qrow = qtile * 64u + warp * 16u + g;
    unsigned gt = (bh * 2048u + qrow) * 2048u + 2u * c + kt * 64u;

    uint32_t keepbits = 0u;
    #pragma unroll
    for (int n = 0; n < 8; ++n) {
        unsigned gi = gt + (unsigned)(8 * n);
        unsigned b00 = threefry_bits_mixed(gi,           p13, p15, p26, p6);
        unsigned b01 = threefry_bits_mixed(gi + 1u,      p13, p15, p26, p6);
        unsigned b10 = threefry_bits_mixed(gi + 16384u,  p13, p15, p26, p6);
        unsigned b11 = threefry_bits_mixed(gi + 16385u,  p13, p15, p26, p6);
        keepbits |= ((~b00) >> 31) << (4 * n + 0);
        keepbits |= ((~b01) >> 31) << (4 * n + 1);
        keepbits |= ((~b10) >> 31) << (4 * n + 2);
        keepbits |= ((~b11) >> 31) << (4 * n + 3);
    }
    g_mask[idx] = keepbits;
}

__device__ __forceinline__ uint32_t packh2(__half a, __half b) {
    __half2 h = __halves2half2(a, b);
    return *reinterpret_cast<uint32_t*>(&h);
}
__device__ __forceinline__ void mma_f16(float c[4], const uint32_t a[4],
                                        uint32_t b0, uint32_t b1) {
    asm volatile(
        "mma.sync.aligned.m16n8k16.row.col.f32.f16.f16.f32 "
        "{%0,%1,%2,%3}, {%4,%5,%6,%7}, {%8,%9}, {%0,%1,%2,%3};\n"
        : "+f"(c[0]), "+f"(c[1]), "+f"(c[2]), "+f"(c[3])
        : "r"(a[0]), "r"(a[1]), "r"(a[2]), "r"(a[3]), "r"(b0), "r"(b1));
}
__device__ __forceinline__ void ldsm_x4(uint32_t& r0, uint32_t& r1,
                                        uint32_t& r2, uint32_t& r3, uint32_t addr) {
    asm volatile("ldmatrix.sync.aligned.m8n8.x4.shared.b16 {%0,%1,%2,%3}, [%4];"
                 : "=r"(r0), "=r"(r1), "=r"(r2), "=r"(r3) : "r"(addr));
}
__device__ __forceinline__ void ldsm_x4_t(uint32_t& r0, uint32_t& r1,
                                          uint32_t& r2, uint32_t& r3, uint32_t addr) {
    asm volatile("ldmatrix.sync.aligned.m8n8.x4.trans.shared.b16 {%0,%1,%2,%3}, [%4];"
                 : "=r"(r0), "=r"(r1), "=r"(r2), "=r"(r3) : "r"(addr));
}
__device__ __forceinline__ void cp_async16(uint32_t dst, const void* src) {
    asm volatile("cp.async.cg.shared.global [%0], [%1], 16;" :: "r"(dst), "l"(src));
}
__device__ __forceinline__ void cp_commit() { asm volatile("cp.async.commit_group;"); }
template <int N> __device__ __forceinline__ void cp_wait() {
    asm volatile("cp.async.wait_group %0;" :: "n"(N));
}

__device__ __forceinline__ void stage_k(uint32_t buf_b, int bh, int k0, int tid)
{
    const size_t kbase = (size_t)bh * (S_LEN * D_DIM) + (size_t)k0 * D_DIM;
    #pragma unroll
    for (int it = 0; it < 16; ++it) {
        int id  = tid + it * NT;
        int arr = id >> 10;
        int rem = id & 1023;
        int row = rem >> 4;
        int col = rem & 15;
        uint32_t dst = buf_b + (uint32_t)(arr * TILE_B + row * 272 + col * 16);
        const __half* src = (arr ? g_Kl : g_Kh) + kbase + (size_t)row * D_DIM + col * 8;
        cp_async16(dst, src);
    }
}
__device__ __forceinline__ void stage_v(uint32_t vbuf_b, int bh, int k0, int tid)
{
    const size_t kbase = (size_t)bh * (S_LEN * D_DIM) + (size_t)k0 * D_DIM;
    #pragma unroll
    for (int it = 0; it < 8; ++it) {
        int id  = tid + it * NT;
        int row = id >> 4;
        int col = id & 15;
        cp_async16(vbuf_b + (uint32_t)(row * 272 + col * 16),
                   g_Vh + kbase + (size_t)row * D_DIM + col * 8);
    }
}

__global__ void __launch_bounds__(NT, 2)
attn_mma_kernel(const float* __restrict__ x1,
                const float* __restrict__ x2,
                const float* __restrict__ x3,
                float* __restrict__ out)
{
    extern __shared__ __half smh[];

    const int tid  = threadIdx.x;
    const int warp = tid >> 5;
    const int lane = tid & 31;
    const int g    = lane >> 2;
    const int c    = lane & 3;
    const int bh   = blockIdx.y;
    const int q0   = blockIdx.x * BM;
    const int qrow = q0 + warp * 16 + g;

    const float* Q = x1 + (size_t)bh * (S_LEN * D_DIM);
    const float* R = x2 + (size_t)bh * (S_LEN * D_DIM);
    float* O = out + (size_t)bh * (S_LEN * D_DIM);
    const float scl = (1.0f / x3[bh]) * 1.4426950408889634f;

    const uint32_t* mrow = g_mask
        + ((((size_t)bh * 32 + blockIdx.x) * 4 + warp) * 32) * 32 + lane;

    const uint32_t smem_u32 = (uint32_t)__cvta_generic_to_shared(smh);

    stage_k(smem_u32 + OFF_K0, bh, 0, tid);
    cp_commit();

    // ---- Q fragments resident (hi + lo split) ----
    uint32_t qh[8][4], ql[8][4];
    #pragma unroll
    for (int t = 0; t < 8; ++t) {
        #pragma unroll
        for (int p = 0; p < 4; ++p) {
            int row = qrow + (p & 1) * 8;
            int col = 16 * t + (p >> 1) * 8 + 2 * c;
            float2 v = *reinterpret_cast<const float2*>(Q + (size_t)row * D_DIM + col);
            __half hx = __float2half_rn(v.x), hy = __float2half_rn(v.y);
            __half lx = __float2half_rn(v.x - __half2float(hx));
            __half ly = __float2half_rn(v.y - __half2float(hy));
            qh[t][p] = packh2(hx, hy);
            ql[t][p] = packh2(lx, ly);
        }
    }

    float oacc[16][4];
    #pragma unroll
    for (int i = 0; i < 16; ++i)
        #pragma unroll
        for (int j = 0; j < 4; ++j) oacc[i][j] = 0.0f;
    float m0 = -CUDART_INF_F, m1 = -CUDART_INF_F;
    float l0 = 0.0f, l1 = 0.0f;

    const int lr  = lane & 7;
    const int seg = lane >> 3;
    const uint32_t k_lane_off = (uint32_t)(lr * 272 + ((seg & 1) * 8 + (seg >> 1) * 16) * 2);
    const uint32_t v_lane_off = (uint32_t)(((seg & 1) * 8 + lr) * 272 + ((seg >> 1) * 8) * 2);
    const uint32_t kh_base0 = smem_u32 + k_lane_off;
    const uint32_t kl_base0 = smem_u32 + (uint32_t)TILE_B + k_lane_off;
    const uint32_t vh_base  = smem_u32 + (uint32_t)OFF_V + v_lane_off;

    for (int kt = 0; kt < 32; ++kt) {
        const uint32_t cur = (uint32_t)(kt & 1) * KBUF_B;
        uint32_t keepbits = mrow[kt * 32];

        __syncthreads();

        stage_v(smem_u32 + OFF_V, bh, kt * BN, tid);
        cp_commit();
        if (kt + 1 < 32)
            stage_k(smem_u32 + ((kt & 1) ? OFF_K0 : OFF_K1), bh, (kt + 1) * BN, tid);
        cp_commit();

        cp_wait<2>();
        __syncthreads();

        const uint32_t kh_base = kh_base0 + cur;
        const uint32_t kl_base = kl_base0 + cur;

        // ---- S = Q @ K^T (qh*kh + ql*kh + qh*kl) ----
        float sacc[8][4];
        #pragma unroll
        for (int n = 0; n < 8; ++n) {
            sacc[n][0] = 0.0f; sacc[n][1] = 0.0f;
            sacc[n][2] = 0.0f; sacc[n][3] = 0.0f;
            const uint32_t rowoff = (uint32_t)(n * 8 * 272);
            #pragma unroll
            for (int dp = 0; dp < 4; ++dp) {
                uint32_t bh0, bh1, bh2, bh3, bl0, bl1, bl2, bl3;
                ldsm_x4(bh0, bh1, bh2, bh3, kh_base + rowoff + (uint32_t)(dp * 64));
                ldsm_x4(bl0, bl1, bl2, bl3, kl_base + rowoff + (uint32_t)(dp * 64));
                mma_f16(sacc[n], qh[2 * dp],     bh0, bh1);
                mma_f16(sacc[n], qh[2 * dp + 1], bh2, bh3);
                mma_f16(sacc[n], ql[2 * dp],     bh0, bh1);
                mma_f16(sacc[n], ql[2 * dp + 1], bh2, bh3);
                mma_f16(sacc[n], qh[2 * dp],     bl0, bl1);
                mma_f16(sacc[n], qh[2 * dp + 1], bl2, bl3);
            }
        }

        // ---- online softmax (exp2 domain) ----
        float mx0 = -CUDART_INF_F, mx1 = -CUDART_INF_F;
        #pragma unroll
        for (int n = 0; n < 8; ++n) {
            sacc[n][0] *= scl; sacc[n][1] *= scl;
            sacc[n][2] *= scl; sacc[n][3] *= scl;
            mx0 = fmaxf(mx0, fmaxf(sacc[n][0], sacc[n][1]));
            mx1 = fmaxf(mx1, fmaxf(sacc[n][2], sacc[n][3]));
        }
        mx0 = fmaxf(mx0, __shfl_xor_sync(0xffffffffu, mx0, 1));
        mx0 = fmaxf(mx0, __shfl_xor_sync(0xffffffffu, mx0, 2));
        mx1 = fmaxf(mx1, __shfl_xor_sync(0xffffffffu, mx1, 1));
        mx1 = fmaxf(mx1, __shfl_xor_sync(0xffffffffu, mx1, 2));
        float mn0 = fmaxf(m0, mx0), mn1 = fmaxf(m1, mx1);
        float sc0 = exp2f(m0 - mn0), sc1 = exp2f(m1 - mn1);
        m0 = mn0; m1 = mn1;
        float rs0 = 0.0f, rs1 = 0.0f;
        #pragma unroll
        for (int n = 0; n < 8; ++n) {
            sacc[n][0] = exp2f(sacc[n][0] - mn0);
            sacc[n][1] = exp2f(sacc[n][1] - mn0);
            sacc[n][2] = exp2f(sacc[n][2] - mn1);
            sacc[n][3] = exp2f(sacc[n][3] - mn1);
            rs0 += sacc[n][0] + sacc[n][1];
            rs1 += sacc[n][2] + sacc[n][3];
        }
        rs0 += __shfl_xor_sync(0xffffffffu, rs0, 1);
        rs0 += __shfl_xor_sync(0xffffffffu, rs0, 2);
        rs1 += __shfl_xor_sync(0xffffffffu, rs1, 1);
        rs1 += __shfl_xor_sync(0xffffffffu, rs1, 2);
        l0 = l0 * sc0 + rs0;
        l1 = l1 * sc1 + rs1;
        #pragma unroll
        for (int i = 0; i < 16; ++i) {
            oacc[i][0] *= sc0; oacc[i][1] *= sc0;
            oacc[i][2] *= sc1; oacc[i][3] *= sc1;
        }

        // ---- apply mask bits + pack P ----
        uint32_t pfr[8][2];
        #pragma unroll
        for (int n = 0; n < 8; ++n) {
            float p00 = ((keepbits >> (4 * n + 0)) & 1u) ? sacc[n][0] : 0.0f;
            float p01 = ((keepbits >> (4 * n + 1)) & 1u) ? sacc[n][1] : 0.0f;
            float p10 = ((keepbits >> (4 * n + 2)) & 1u) ? sacc[n][2] : 0.0f;
            float p11 = ((keepbits >> (4 * n + 3)) & 1u) ? sacc[n][3] : 0.0f;
            pfr[n][0] = packh2(__float2half_rn(p00), __float2half_rn(p01));
            pfr[n][1] = packh2(__float2half_rn(p10), __float2half_rn(p11));
        }

        cp_wait<1>();
        __syncthreads();

        // ---- O += P @ V ----
        #pragma unroll
        for (int kk = 0; kk < 4; ++kk) {
            uint32_t a[4] = { pfr[2 * kk][0], pfr[2 * kk][1],
                              pfr[2 * kk + 1][0], pfr[2 * kk + 1][1] };
            const uint32_t kkoff = (uint32_t)(kk * 16 * 272);
            #pragma unroll
            for (int np = 0; np < 8; ++np) {
                uint32_t b0, b1, b2, b3;
                ldsm_x4_t(b0, b1, b2, b3, vh_base + kkoff + (uint32_t)(np * 32));
                mma_f16(oacc[2 * np],     a, b0, b1);
                mma_f16(oacc[2 * np + 1], a, b2, b3);
            }
        }
    }

    // ---- epilogue: out = 2*o/l + residual(x2) ----
    const float il0 = 2.0f / l0;
    const float il1 = 2.0f / l1;
    #pragma unroll
    for (int np = 0; np < 16; ++np) {
        int col = 8 * np + 2 * c;
        const float2 r0 = *reinterpret_cast<const float2*>(R + (size_t)qrow * D_DIM + col);
        const float2 r1 = *reinterpret_cast<const float2*>(R + (size_t)(qrow + 8) * D_DIM + col);
        float2 w0, w1;
        w0.x = fmaf(oacc[np][0], il0, r0.x);
        w0.y = fmaf(oacc[np][1], il0, r0.y);
        w1.x = fmaf(oacc[np][2], il1, r1.x);
        w1.y = fmaf(oacc[np][3], il1, r1.y);
        *reinterpret_cast<float2*>(O + (size_t)qrow * D_DIM + col) = w0;
        *reinterpret_cast<float2*>(O + (size_t)(qrow + 8) * D_DIM + col) = w1;
    }
}

extern "C" void kernel_launch(void* const* d_in, const int* in_sizes, int n_in,
                              void* d_out, int out_size) {
    const float* x1 = (const float*)d_in[0];
    const float* x2 = (const float*)d_in[1];
    const float* x3 = (const float*)d_in[2];
    float* out = (float*)d_out;
    (void)in_sizes; (void)n_in; (void)out_size;

    cudaFuncSetAttribute(attn_mma_kernel,
                         cudaFuncAttributeMaxDynamicSharedMemorySize, SMEM_BYTES);

    convert_kernel<<<1024, 256>>>(x1, x2);
    mask_kernel<<<NMASKW / 256, 256>>>();
    dim3 grid(S_LEN / BM, 32);
    attn_mma_kernel<<<grid, NT, SMEM_BYTES>>>(x1, x2, x3, out);
}